// round 13
// baseline (speedup 1.0000x reference)
#include <cuda_runtime.h>
#include <cuda_bf16.h>
#include <cstdint>

// ============================================================================
// KoopmanOperator: z_{t+1} = z + DT*(z@A^T + sum_l a_l * U_l (V_l^T z))
// N=262144 rows, m=256, da=6, r=16, steps=8.
//
// R13 = R11 (254us) with the precompute chain tightened:
//  * koop_gemm3: single-shot SMEM GEMM (32x256 A-slab + 256x32 B-slab, 70KB,
//    MLP-16 load, one sync) replaces the chunked double-buffer kernel that
//    measured 13us/launch at regs=252.
//  * init merged into level-1 launch (X2 computed from A via on-the-fly
//    X = dt*A + I transform; no g_X dependency for job 0).
// Hot kernel identical to R9/R11 (mma.sync bf16 fused-operator single pass,
// z = fp32 D-fragment accumulator; steps=8 -> P=8, passes=1).
//
// Fusion: z_out = (X + dt B)^P z ≈ X^P z + P*dt*(X^{P/2} U)(V^T X^{P-1-P/2}) z
// ============================================================================

#define DT_C    0.1f
#define BMAX_C  0.3f

static constexpr int M_DIM  = 256;
static constexpr int TILE_M = 128;   // rows per CTA (8 warps x 16)

// Fragment-ordered weight images (bf16), 512B frag-pair units:
//   BA: X^P - I   [kc2 0..8)][nc 0..32)] -> 131072 B
//   BV: Vhat      [kc2 0..8)][nc 0..12)] ->  49152 B
//   BU: P*dt*Uhat [kc2 0..3)][nc 0..32)] ->  49152 B
static constexpr int BA_BYTES = 8 * 32 * 512;
static constexpr int BV_BYTES = 8 * 12 * 512;
static constexpr int BU_BYTES = 3 * 32 * 512;
static constexpr int W_TOTAL  = BA_BYTES + BV_BYTES + BU_BYTES;  // 229376

__device__ __align__(16) unsigned char g_wfrag[W_TOTAL];

// fp32 precompute scratch
__device__ __align__(16) float g_X [65536];
__device__ __align__(16) float g_X2[65536];
__device__ __align__(16) float g_X4[65536];
__device__ __align__(16) float g_X8[65536];
__device__ __align__(16) float g_Um[24576];   // [m][lr]
__device__ __align__(16) float g_Vm[24576];   // [m][lr]
__device__ __align__(16) float g_T [24576];   // [m][lr]  X2^T * Vm (P=8)
__device__ __align__(16) float g_Uh[24576];   // [m][lr]  E1 * Um
__device__ __align__(16) float g_Vh[24576];   // [m][lr]  E2^T * Vm

__device__ __forceinline__ int pick_P(int steps) {
    if (steps > 0 && (steps % 8) == 0) return 8;
    if (steps > 0 && (steps % 4) == 0) return 4;
    if (steps > 0 && (steps % 2) == 0) return 2;
    return 1;
}

// ============================================================================
// helpers
// ============================================================================
__device__ __forceinline__ uint32_t smem_u32(const void* p) {
    uint32_t a;
    asm("{ .reg .u64 t; cvta.to.shared.u64 t, %1; cvt.u32.u64 %0, t; }"
        : "=r"(a) : "l"(p));
    return a;
}

// pack bf16x2: lo -> low 16 bits (first PTX src -> HIGH half).
__device__ __forceinline__ uint32_t packbf(float lo, float hi) {
    uint32_t r;
    asm("cvt.rn.satfinite.bf16x2.f32 %0, %1, %2;" : "=r"(r) : "f"(hi), "f"(lo));
    return r;
}

__device__ __forceinline__ void lds128(uint32_t& x, uint32_t& y,
                                       uint32_t& z, uint32_t& w, uint32_t addr) {
    asm volatile("ld.shared.v4.b32 {%0,%1,%2,%3}, [%4];"
                 : "=r"(x), "=r"(y), "=r"(z), "=r"(w) : "r"(addr));
}

__device__ __forceinline__ void mma_bf16(float& d0, float& d1, float& d2, float& d3,
                                         uint32_t a0, uint32_t a1, uint32_t a2,
                                         uint32_t a3, uint32_t b0, uint32_t b1) {
    asm volatile(
        "mma.sync.aligned.m16n8k16.row.col.f32.bf16.bf16.f32 "
        "{%0,%1,%2,%3}, {%4,%5,%6,%7}, {%8,%9}, {%0,%1,%2,%3};"
        : "+f"(d0), "+f"(d1), "+f"(d2), "+f"(d3)
        : "r"(a0), "r"(a1), "r"(a2), "r"(a3), "r"(b0), "r"(b1));
}

// ============================================================================
// Precompute GEMM, single-shot SMEM: C[256,N] = op(A)[256,256] * B[256,N].
// 32x32 output tiles, 256 threads, 2x2 micro-tile. Full 32x256 A-slab and
// 256x32 B-slab staged in SMEM (70KB) with 16 float4/thread in flight,
// ONE __syncthreads, then a straight 256-k FMA loop.
// job = job_base + blockIdx.z:
//  0: X2 = X*X (X built on the fly from A: dt*A + I)
//  1: init: g_X, g_Um, g_Vm                      (grid-strided, no GEMM)
//  2: X4 = X2*X2        3: T  = X2^T*Vm (P=8) | copy Vm        [N=96]
//  4: X8 = X4*X4        5: Uh = E1*Um | copy (E1 = X^{P/2})    [N=96]
//                       6: Vh = X^T*T (P>=4) | copy T          [N=96]
// ============================================================================
static constexpr int AS_PITCH = 260;    // floats; 16B-aligned, bank-spread
static constexpr int BS_PITCH = 36;     // floats; 16B-aligned, bank-spread
static constexpr int G3_SMEM  = (32 * AS_PITCH + 256 * BS_PITCH) * 4;  // 70144

__global__ void __launch_bounds__(256, 1)
koop_gemm3(int job_base,
           const float* __restrict__ Araw,
           const float* __restrict__ BUraw,
           const float* __restrict__ BVraw,
           const int* __restrict__ steps_p) {
    int job = job_base + (int)blockIdx.z;
    int steps = steps_p ? *steps_p : 8;
    int P = pick_P(steps);
    int tid = threadIdx.x;

    if (job == 1) {     // ---- init: X = I + dt*A ; Um/Vm as [m][lr] ----
        int base = ((int)blockIdx.y * 8 + (int)blockIdx.x) * 256 + tid;
        for (int id = base; id < 65536; id += 16384) {
            int n = id >> 8, k = id & 255;
            g_X[id] = DT_C * Araw[id] + (n == k ? 1.f : 0.f);
        }
        for (int id = base; id < 24576; id += 16384) {
            int m = id / 96, lr = id % 96, l = lr >> 4, ri = lr & 15;
            g_Um[id] = tanhf(BUraw[(l * 256 + m) * 16 + ri]) * BMAX_C;
            g_Vm[id] = tanhf(BVraw[(l * 256 + m) * 16 + ri]) * BMAX_C;
        }
        return;
    }

    const float *Ap = nullptr, *Bp = nullptr;
    float* Cp = nullptr;
    int N = 256; bool tA = false, ident = false, xform = false;
    switch (job) {
    case 0: Ap = Araw; Bp = Araw; Cp = g_X2; xform = true; break;
    case 2: Ap = g_X2; Bp = g_X2; Cp = g_X4; break;
    case 3: N = 96; Bp = g_Vm; Cp = g_T; tA = true;
            if (P == 8) Ap = g_X2; else ident = true; break;
    case 4: Ap = g_X4; Bp = g_X4; Cp = g_X8; break;
    case 5: N = 96; Bp = g_Um; Cp = g_Uh;
            if (P == 8) Ap = g_X4; else if (P == 4) Ap = g_X2;
            else if (P == 2) Ap = g_X; else ident = true; break;
    default: N = 96; Bp = g_T; Cp = g_Vh; tA = true;
            if (P >= 4) Ap = g_X; else ident = true; break;
    }

    int row0 = blockIdx.y * 32, col0 = blockIdx.x * 32;
    if (col0 >= N) return;

    if (ident) {
        for (int q = tid; q < 32 * 32; q += 256) {
            int i = q >> 5, j = q & 31;
            Cp[(row0 + i) * N + col0 + j] = Bp[(row0 + i) * N + col0 + j];
        }
        return;
    }

    extern __shared__ float sm3[];
    float* As = sm3;                    // [32][AS_PITCH]: As[i][k]=op(A)[row0+i][k]
    float* Bs = sm3 + 32 * AS_PITCH;    // [256][BS_PITCH]: Bs[k][j]=B[k][col0+j]

    // ---- stage A slab ----
    if (!tA) {
        for (int q = tid; q < 2048; q += 256) {
            int i = q >> 6, kk = (q & 63) * 4;
            float4 v = *reinterpret_cast<const float4*>(Ap + (row0 + i) * 256 + kk);
            if (xform) {
                int rr = row0 + i;
                v.x = DT_C * v.x + (rr == kk     ? 1.f : 0.f);
                v.y = DT_C * v.y + (rr == kk + 1 ? 1.f : 0.f);
                v.z = DT_C * v.z + (rr == kk + 2 ? 1.f : 0.f);
                v.w = DT_C * v.w + (rr == kk + 3 ? 1.f : 0.f);
            }
            *reinterpret_cast<float4*>(As + i * AS_PITCH + kk) = v;
        }
    } else {            // As[i][k] = A[k][row0+i]  (contiguous in i)
        for (int q = tid; q < 2048; q += 256) {
            int k = q >> 3, ii = (q & 7) * 4;
            float4 v = *reinterpret_cast<const float4*>(Ap + k * 256 + row0 + ii);
            As[(ii + 0) * AS_PITCH + k] = v.x;
            As[(ii + 1) * AS_PITCH + k] = v.y;
            As[(ii + 2) * AS_PITCH + k] = v.z;
            As[(ii + 3) * AS_PITCH + k] = v.w;
        }
    }
    // ---- stage B slab ----
    for (int q = tid; q < 2048; q += 256) {
        int k = q >> 3, jj = (q & 7) * 4;
        float4 v = *reinterpret_cast<const float4*>(Bp + k * N + col0 + jj);
        if (xform) {
            int cc = col0 + jj;
            v.x = DT_C * v.x + (k == cc     ? 1.f : 0.f);
            v.y = DT_C * v.y + (k == cc + 1 ? 1.f : 0.f);
            v.z = DT_C * v.z + (k == cc + 2 ? 1.f : 0.f);
            v.w = DT_C * v.w + (k == cc + 3 ? 1.f : 0.f);
        }
        *reinterpret_cast<float4*>(Bs + k * BS_PITCH + jj) = v;
    }
    __syncthreads();

    // ---- compute 2x2 micro-tile ----
    int tx = tid & 15, ty = tid >> 4;
    const float* ar0 = As + (ty * 2) * AS_PITCH;
    const float* ar1 = ar0 + AS_PITCH;
    float c00 = 0.f, c01 = 0.f, c10 = 0.f, c11 = 0.f;
#pragma unroll 8
    for (int k = 0; k < 256; k++) {
        float2 b = *reinterpret_cast<const float2*>(Bs + k * BS_PITCH + tx * 2);
        float a0 = ar0[k], a1 = ar1[k];
        c00 += a0 * b.x; c01 += a0 * b.y;
        c10 += a1 * b.x; c11 += a1 * b.y;
    }

    int rr = row0 + ty * 2, cc = col0 + tx * 2;
    Cp[rr * N + cc] = c00;       Cp[rr * N + cc + 1] = c01;
    Cp[(rr + 1) * N + cc] = c10; Cp[(rr + 1) * N + cc + 1] = c11;
}

// ============================================================================
// Precompute stage 3: fragment images.
//  BA: W[n][k] = (X^P)[n][k] - I ;  BV: W[n=lr][k=m] = Vh[m][lr]
//  BU: W[n][k=lr] = P*dt * Uh[n][lr]
// bf16 B-frag (m16n8k16 row.col): lane l: b0={W[n][k0],W[n][k0+1]},
//   b1={W[n][k0+8],W[n][k0+9]}; n=8nc+(l>>2), k0=16kc+(l&3)*2.
// ============================================================================
__global__ void koop_frag(const int* __restrict__ steps_p) {
    int steps = steps_p ? *steps_p : 8;
    int P = pick_P(steps);
    const float* AP = (P == 8) ? g_X8 : (P == 4) ? g_X4 : (P == 2) ? g_X2 : g_X;
    float coefU = (float)P * DT_C;

    int id = blockIdx.x * blockDim.x + threadIdx.x;
    if (id >= W_TOTAL / 4) return;

    int r = id & 3, lane = (id >> 2) & 31, rest = id >> 7;
    int tig = lane & 3, lg = lane >> 2;
    int kodd = r >> 1, breg = r & 1;

    float lo, hi;
    if (id < BA_BYTES / 4) {
        int nc = rest & 31, kc2 = rest >> 5;
        int n  = 8 * nc + lg;
        int k0 = 16 * (2 * kc2 + kodd) + tig * 2 + breg * 8;
        lo = AP[n * 256 + k0]     - (n == k0     ? 1.f : 0.f);
        hi = AP[n * 256 + k0 + 1] - (n == k0 + 1 ? 1.f : 0.f);
    } else if (id < (BA_BYTES + BV_BYTES) / 4) {
        int rest2 = rest - (BA_BYTES / 512);
        int nc = rest2 % 12, kc2 = rest2 / 12;
        int n  = 8 * nc + lg;                      // lr index [0,96)
        int k0 = 16 * (2 * kc2 + kodd) + tig * 2 + breg * 8;
        lo = g_Vh[k0 * 96 + n];
        hi = g_Vh[(k0 + 1) * 96 + n];
    } else {
        int rest3 = rest - ((BA_BYTES + BV_BYTES) / 512);
        int nc = rest3 & 31, kc2 = rest3 >> 5;     // kc2 in [0,3)
        int n  = 8 * nc + lg;                      // output col [0,256)
        int k0 = 16 * (2 * kc2 + kodd) + tig * 2 + breg * 8;  // lr [0,96)
        lo = coefU * g_Uh[n * 96 + k0];
        hi = coefU * g_Uh[n * 96 + k0 + 1];
    }
    reinterpret_cast<uint32_t*>(g_wfrag)[id] = packbf(lo, hi);
}

// ============================================================================
// Main persistent kernel (unchanged, proven): 256 threads, 8 warps x 16 rows,
// passes = steps/P (8 -> 1 pass).
// ============================================================================
__global__ void __launch_bounds__(256, 1)
koop_main(const float* __restrict__ z_in, const float* __restrict__ a_in,
          const int* __restrict__ steps_p, float* __restrict__ out, int n_tiles) {
    extern __shared__ unsigned char smem[];
    int tid = threadIdx.x, wid = tid >> 5, lane = tid & 31;
    int tig = lane & 3, lg = lane >> 2;

    {
        const uint4* src = reinterpret_cast<const uint4*>(g_wfrag);
        uint4* dst = reinterpret_cast<uint4*>(smem);
        for (int i = tid; i < W_TOTAL / 16; i += 256) dst[i] = src[i];
    }
    __syncthreads();

    const uint32_t sbA = smem_u32(smem) + (uint32_t)lane * 16;
    const uint32_t sbV = sbA + BA_BYTES;
    const uint32_t sbU = sbA + BA_BYTES + BV_BYTES;

    int steps = steps_p ? *steps_p : 8;
    int P = pick_P(steps);
    int passes = (steps > 0) ? steps / P : 0;

    for (int tile = blockIdx.x; tile < n_tiles; tile += gridDim.x) {
        int r0 = tile * TILE_M + wid * 16 + lg;
        const float2* zr0 = reinterpret_cast<const float2*>(z_in + (size_t)r0 * M_DIM);
        const float2* zr1 = reinterpret_cast<const float2*>(z_in + (size_t)(r0 + 8) * M_DIM);

        float acc[32][4];
#pragma unroll
        for (int nc = 0; nc < 32; nc++) {
            float2 v0 = zr0[4 * nc + tig];
            float2 v1 = zr1[4 * nc + tig];
            acc[nc][0] = v0.x; acc[nc][1] = v0.y;
            acc[nc][2] = v1.x; acc[nc][3] = v1.y;
        }
        float av0[6], av1[6];
#pragma unroll
        for (int l = 0; l < 6; l++) {
            av0[l] = a_in[(size_t)r0 * 6 + l];
            av1[l] = a_in[(size_t)(r0 + 8) * 6 + l];
        }

#pragma unroll 1
        for (int s = 0; s < passes; s++) {
            uint32_t af[16][4];
#pragma unroll
            for (int kc = 0; kc < 16; kc++) {
                af[kc][0] = packbf(acc[2 * kc][0],     acc[2 * kc][1]);
                af[kc][1] = packbf(acc[2 * kc][2],     acc[2 * kc][3]);
                af[kc][2] = packbf(acc[2 * kc + 1][0], acc[2 * kc + 1][1]);
                af[kc][3] = packbf(acc[2 * kc + 1][2], acc[2 * kc + 1][3]);
            }

            // ---- A-GEMM: acc += z @ (X^P - I)^T ----
#pragma unroll
            for (int i = 0; i < 256; i++) {
                uint32_t b0, b1, b2, b3;
                lds128(b0, b1, b2, b3, sbA + (uint32_t)i * 512);
                int kc2 = i >> 5, nc = i & 31;
                mma_bf16(acc[nc][0], acc[nc][1], acc[nc][2], acc[nc][3],
                         af[2 * kc2][0], af[2 * kc2][1],
                         af[2 * kc2][2], af[2 * kc2][3], b0, b1);
                mma_bf16(acc[nc][0], acc[nc][1], acc[nc][2], acc[nc][3],
                         af[2 * kc2 + 1][0], af[2 * kc2 + 1][1],
                         af[2 * kc2 + 1][2], af[2 * kc2 + 1][3], b2, b3);
            }

            // ---- V-proj: proj = z @ Vhat^T (N=96), scale by a_l, pack ----
            uint32_t paf[6][4];
#pragma unroll
            for (int ncp = 0; ncp < 6; ncp++) {
                float p0[4] = {0.f, 0.f, 0.f, 0.f};
                float p1[4] = {0.f, 0.f, 0.f, 0.f};
#pragma unroll
                for (int kc2 = 0; kc2 < 8; kc2++) {
                    uint32_t b0, b1, b2, b3;
                    uint32_t base = sbV + (uint32_t)(kc2 * 12 + 2 * ncp) * 512;
                    lds128(b0, b1, b2, b3, base);
                    mma_bf16(p0[0], p0[1], p0[2], p0[3],
                             af[2 * kc2][0], af[2 * kc2][1],
                             af[2 * kc2][2], af[2 * kc2][3], b0, b1);
                    mma_bf16(p0[0], p0[1], p0[2], p0[3],
                             af[2 * kc2 + 1][0], af[2 * kc2 + 1][1],
                             af[2 * kc2 + 1][2], af[2 * kc2 + 1][3], b2, b3);
                    lds128(b0, b1, b2, b3, base + 512);
                    mma_bf16(p1[0], p1[1], p1[2], p1[3],
                             af[2 * kc2][0], af[2 * kc2][1],
                             af[2 * kc2][2], af[2 * kc2][3], b0, b1);
                    mma_bf16(p1[0], p1[1], p1[2], p1[3],
                             af[2 * kc2 + 1][0], af[2 * kc2 + 1][1],
                             af[2 * kc2 + 1][2], af[2 * kc2 + 1][3], b2, b3);
                }
                paf[ncp][0] = packbf(p0[0] * av0[ncp], p0[1] * av0[ncp]);
                paf[ncp][1] = packbf(p0[2] * av1[ncp], p0[3] * av1[ncp]);
                paf[ncp][2] = packbf(p1[0] * av0[ncp], p1[1] * av0[ncp]);
                paf[ncp][3] = packbf(p1[2] * av1[ncp], p1[3] * av1[ncp]);
            }

            // ---- U-GEMM: acc += pa @ (P*dt*Uhat)^T ----
#pragma unroll
            for (int i = 0; i < 96; i++) {
                uint32_t b0, b1, b2, b3;
                lds128(b0, b1, b2, b3, sbU + (uint32_t)i * 512);
                int kc2 = i >> 5, nc = i & 31;
                mma_bf16(acc[nc][0], acc[nc][1], acc[nc][2], acc[nc][3],
                         paf[2 * kc2][0], paf[2 * kc2][1],
                         paf[2 * kc2][2], paf[2 * kc2][3], b0, b1);
                mma_bf16(acc[nc][0], acc[nc][1], acc[nc][2], acc[nc][3],
                         paf[2 * kc2 + 1][0], paf[2 * kc2 + 1][1],
                         paf[2 * kc2 + 1][2], paf[2 * kc2 + 1][3], b2, b3);
            }
        }

        float2* o0 = reinterpret_cast<float2*>(out + (size_t)r0 * M_DIM);
        float2* o1 = reinterpret_cast<float2*>(out + (size_t)(r0 + 8) * M_DIM);
#pragma unroll
        for (int nc = 0; nc < 32; nc++) {
            o0[4 * nc + tig] = make_float2(acc[nc][0], acc[nc][1]);
            o1[4 * nc + tig] = make_float2(acc[nc][2], acc[nc][3]);
        }
    }
}

// ============================================================================
// kernel_launch — graph-capturable: kernel launches only, no sync, no alloc.
// ============================================================================
extern "C" void kernel_launch(void* const* d_in, const int* in_sizes, int n_in,
                              void* d_out, int out_size) {
    const float* z  = (const float*)d_in[0];
    const float* a  = (const float*)d_in[1];
    const float* A  = (const float*)d_in[2];
    const float* BU = (const float*)d_in[3];
    const float* BV = (const float*)d_in[4];
    const int* steps = (n_in > 5) ? (const int*)d_in[5] : nullptr;

    int n_rows  = in_sizes[0] / M_DIM;
    int n_tiles = n_rows / TILE_M;

    cudaFuncSetAttribute(koop_main, cudaFuncAttributeMaxDynamicSharedMemorySize,
                         W_TOTAL);
    cudaFuncSetAttribute(koop_gemm3, cudaFuncAttributeMaxDynamicSharedMemorySize,
                         G3_SMEM);

    // Precompute levels: {X2, init} -> {X4, T} -> {X8, Uh, Vh} -> frag
    koop_gemm3<<<dim3(8, 8, 2), 256, G3_SMEM>>>(0, A, BU, BV, steps);
    koop_gemm3<<<dim3(8, 8, 2), 256, G3_SMEM>>>(2, A, BU, BV, steps);
    koop_gemm3<<<dim3(8, 8, 3), 256, G3_SMEM>>>(4, A, BU, BV, steps);
    koop_frag<<<(W_TOTAL / 4 + 255) / 256, 256>>>(steps);

    int dev = 0, sm_count = 0;
    cudaGetDevice(&dev);
    cudaDeviceGetAttribute(&sm_count, cudaDevAttrMultiProcessorCount, dev);
    if (sm_count <= 0) sm_count = 148;
    int grid = n_tiles < sm_count ? n_tiles : sm_count;

    koop_main<<<grid, 256, W_TOTAL>>>(z, a, steps, (float*)d_out, n_tiles);
}

// round 14
// speedup vs baseline: 1.0491x; 1.0491x over previous
#include <cuda_runtime.h>
#include <cuda_bf16.h>
#include <cstdint>

// ============================================================================
// KoopmanOperator: z_{t+1} = z + DT*(z@A^T + sum_l a_l * U_l (V_l^T z))
// N=262144 rows, m=256, da=6, r=16, steps=8.
//
// R14 = R13 + z-stream L2 pipelining in the hot kernel:
//  * each warp issues prefetch.global.L2 for its NEXT tile's z rows (and a)
//    at the start of the current tile's ~10us compute -> next tile's loads
//    hit L2 instead of being DRAM-BW exposed (~2.5us/tile serial).
//  * z reads via __ldcs (read-once, evict-first), out stores via __stcs
//    (streaming) to keep prefetched data resident in L2.
// Precompute chain as R13 (single-shot SMEM GEMMs, init merged, 5 launches).
//
// Fusion: z_out = (X + dt B)^P z ≈ X^P z + P*dt*(X^{P/2} U)(V^T X^{P-1-P/2}) z
// with X = I + dt*A; steps=8 -> P=8, one pass. Hot loop: mma.sync bf16,
// z = fp32 D-fragment accumulator (identity exact).
// ============================================================================

#define DT_C    0.1f
#define BMAX_C  0.3f

static constexpr int M_DIM  = 256;
static constexpr int TILE_M = 128;   // rows per CTA (8 warps x 16)

// Fragment-ordered weight images (bf16), 512B frag-pair units:
//   BA: X^P - I   [kc2 0..8)][nc 0..32)] -> 131072 B
//   BV: Vhat      [kc2 0..8)][nc 0..12)] ->  49152 B
//   BU: P*dt*Uhat [kc2 0..3)][nc 0..32)] ->  49152 B
static constexpr int BA_BYTES = 8 * 32 * 512;
static constexpr int BV_BYTES = 8 * 12 * 512;
static constexpr int BU_BYTES = 3 * 32 * 512;
static constexpr int W_TOTAL  = BA_BYTES + BV_BYTES + BU_BYTES;  // 229376

__device__ __align__(16) unsigned char g_wfrag[W_TOTAL];

// fp32 precompute scratch
__device__ __align__(16) float g_X [65536];
__device__ __align__(16) float g_X2[65536];
__device__ __align__(16) float g_X4[65536];
__device__ __align__(16) float g_X8[65536];
__device__ __align__(16) float g_Um[24576];   // [m][lr]
__device__ __align__(16) float g_Vm[24576];   // [m][lr]
__device__ __align__(16) float g_T [24576];   // [m][lr]  X2^T * Vm (P=8)
__device__ __align__(16) float g_Uh[24576];   // [m][lr]  E1 * Um
__device__ __align__(16) float g_Vh[24576];   // [m][lr]  E2^T * Vm

__device__ __forceinline__ int pick_P(int steps) {
    if (steps > 0 && (steps % 8) == 0) return 8;
    if (steps > 0 && (steps % 4) == 0) return 4;
    if (steps > 0 && (steps % 2) == 0) return 2;
    return 1;
}

// ============================================================================
// helpers
// ============================================================================
__device__ __forceinline__ uint32_t smem_u32(const void* p) {
    uint32_t a;
    asm("{ .reg .u64 t; cvta.to.shared.u64 t, %1; cvt.u32.u64 %0, t; }"
        : "=r"(a) : "l"(p));
    return a;
}

// pack bf16x2: lo -> low 16 bits (first PTX src -> HIGH half).
__device__ __forceinline__ uint32_t packbf(float lo, float hi) {
    uint32_t r;
    asm("cvt.rn.satfinite.bf16x2.f32 %0, %1, %2;" : "=r"(r) : "f"(hi), "f"(lo));
    return r;
}

__device__ __forceinline__ void lds128(uint32_t& x, uint32_t& y,
                                       uint32_t& z, uint32_t& w, uint32_t addr) {
    asm volatile("ld.shared.v4.b32 {%0,%1,%2,%3}, [%4];"
                 : "=r"(x), "=r"(y), "=r"(z), "=r"(w) : "r"(addr));
}

__device__ __forceinline__ void mma_bf16(float& d0, float& d1, float& d2, float& d3,
                                         uint32_t a0, uint32_t a1, uint32_t a2,
                                         uint32_t a3, uint32_t b0, uint32_t b1) {
    asm volatile(
        "mma.sync.aligned.m16n8k16.row.col.f32.bf16.bf16.f32 "
        "{%0,%1,%2,%3}, {%4,%5,%6,%7}, {%8,%9}, {%0,%1,%2,%3};"
        : "+f"(d0), "+f"(d1), "+f"(d2), "+f"(d3)
        : "r"(a0), "r"(a1), "r"(a2), "r"(a3), "r"(b0), "r"(b1));
}

__device__ __forceinline__ void prefetch_l2(const void* p) {
    asm volatile("prefetch.global.L2 [%0];" :: "l"(p));
}

// ============================================================================
// Precompute GEMM, single-shot SMEM: C[256,N] = op(A)[256,256] * B[256,N].
// 32x32 output tiles, 256 threads, 2x2 micro-tile. Full 32x256 A-slab and
// 256x32 B-slab staged in SMEM (70KB), ONE __syncthreads, straight k loop.
// job = job_base + blockIdx.z:
//  0: X2 = X*X (X built on the fly from A: dt*A + I)
//  1: init: g_X, g_Um, g_Vm                      (grid-strided, no GEMM)
//  2: X4 = X2*X2        3: T  = X2^T*Vm (P=8) | copy Vm        [N=96]
//  4: X8 = X4*X4        5: Uh = E1*Um | copy (E1 = X^{P/2})    [N=96]
//                       6: Vh = X^T*T (P>=4) | copy T          [N=96]
// ============================================================================
static constexpr int AS_PITCH = 260;
static constexpr int BS_PITCH = 36;
static constexpr int G3_SMEM  = (32 * AS_PITCH + 256 * BS_PITCH) * 4;  // 70144

__global__ void __launch_bounds__(256, 1)
koop_gemm3(int job_base,
           const float* __restrict__ Araw,
           const float* __restrict__ BUraw,
           const float* __restrict__ BVraw,
           const int* __restrict__ steps_p) {
    int job = job_base + (int)blockIdx.z;
    int steps = steps_p ? *steps_p : 8;
    int P = pick_P(steps);
    int tid = threadIdx.x;

    if (job == 1) {     // ---- init: X = I + dt*A ; Um/Vm as [m][lr] ----
        int base = ((int)blockIdx.y * 8 + (int)blockIdx.x) * 256 + tid;
        for (int id = base; id < 65536; id += 16384) {
            int n = id >> 8, k = id & 255;
            g_X[id] = DT_C * Araw[id] + (n == k ? 1.f : 0.f);
        }
        for (int id = base; id < 24576; id += 16384) {
            int m = id / 96, lr = id % 96, l = lr >> 4, ri = lr & 15;
            g_Um[id] = tanhf(BUraw[(l * 256 + m) * 16 + ri]) * BMAX_C;
            g_Vm[id] = tanhf(BVraw[(l * 256 + m) * 16 + ri]) * BMAX_C;
        }
        return;
    }

    const float *Ap = nullptr, *Bp = nullptr;
    float* Cp = nullptr;
    int N = 256; bool tA = false, ident = false, xform = false;
    switch (job) {
    case 0: Ap = Araw; Bp = Araw; Cp = g_X2; xform = true; break;
    case 2: Ap = g_X2; Bp = g_X2; Cp = g_X4; break;
    case 3: N = 96; Bp = g_Vm; Cp = g_T; tA = true;
            if (P == 8) Ap = g_X2; else ident = true; break;
    case 4: Ap = g_X4; Bp = g_X4; Cp = g_X8; break;
    case 5: N = 96; Bp = g_Um; Cp = g_Uh;
            if (P == 8) Ap = g_X4; else if (P == 4) Ap = g_X2;
            else if (P == 2) Ap = g_X; else ident = true; break;
    default: N = 96; Bp = g_T; Cp = g_Vh; tA = true;
            if (P >= 4) Ap = g_X; else ident = true; break;
    }

    int row0 = blockIdx.y * 32, col0 = blockIdx.x * 32;
    if (col0 >= N) return;

    if (ident) {
        for (int q = tid; q < 32 * 32; q += 256) {
            int i = q >> 5, j = q & 31;
            Cp[(row0 + i) * N + col0 + j] = Bp[(row0 + i) * N + col0 + j];
        }
        return;
    }

    extern __shared__ float sm3[];
    float* As = sm3;                    // [32][AS_PITCH]
    float* Bs = sm3 + 32 * AS_PITCH;    // [256][BS_PITCH]

    if (!tA) {
        for (int q = tid; q < 2048; q += 256) {
            int i = q >> 6, kk = (q & 63) * 4;
            float4 v = *reinterpret_cast<const float4*>(Ap + (row0 + i) * 256 + kk);
            if (xform) {
                int rr = row0 + i;
                v.x = DT_C * v.x + (rr == kk     ? 1.f : 0.f);
                v.y = DT_C * v.y + (rr == kk + 1 ? 1.f : 0.f);
                v.z = DT_C * v.z + (rr == kk + 2 ? 1.f : 0.f);
                v.w = DT_C * v.w + (rr == kk + 3 ? 1.f : 0.f);
            }
            *reinterpret_cast<float4*>(As + i * AS_PITCH + kk) = v;
        }
    } else {
        for (int q = tid; q < 2048; q += 256) {
            int k = q >> 3, ii = (q & 7) * 4;
            float4 v = *reinterpret_cast<const float4*>(Ap + k * 256 + row0 + ii);
            As[(ii + 0) * AS_PITCH + k] = v.x;
            As[(ii + 1) * AS_PITCH + k] = v.y;
            As[(ii + 2) * AS_PITCH + k] = v.z;
            As[(ii + 3) * AS_PITCH + k] = v.w;
        }
    }
    for (int q = tid; q < 2048; q += 256) {
        int k = q >> 3, jj = (q & 7) * 4;
        float4 v = *reinterpret_cast<const float4*>(Bp + k * N + col0 + jj);
        if (xform) {
            int cc = col0 + jj;
            v.x = DT_C * v.x + (k == cc     ? 1.f : 0.f);
            v.y = DT_C * v.y + (k == cc + 1 ? 1.f : 0.f);
            v.z = DT_C * v.z + (k == cc + 2 ? 1.f : 0.f);
            v.w = DT_C * v.w + (k == cc + 3 ? 1.f : 0.f);
        }
        *reinterpret_cast<float4*>(Bs + k * BS_PITCH + jj) = v;
    }
    __syncthreads();

    int tx = tid & 15, ty = tid >> 4;
    const float* ar0 = As + (ty * 2) * AS_PITCH;
    const float* ar1 = ar0 + AS_PITCH;
    float c00 = 0.f, c01 = 0.f, c10 = 0.f, c11 = 0.f;
#pragma unroll 8
    for (int k = 0; k < 256; k++) {
        float2 b = *reinterpret_cast<const float2*>(Bs + k * BS_PITCH + tx * 2);
        float a0 = ar0[k], a1 = ar1[k];
        c00 += a0 * b.x; c01 += a0 * b.y;
        c10 += a1 * b.x; c11 += a1 * b.y;
    }

    int rr = row0 + ty * 2, cc = col0 + tx * 2;
    Cp[rr * N + cc] = c00;       Cp[rr * N + cc + 1] = c01;
    Cp[(rr + 1) * N + cc] = c10; Cp[(rr + 1) * N + cc + 1] = c11;
}

// ============================================================================
// Precompute stage 3: fragment images.
//  BA: W[n][k] = (X^P)[n][k] - I ;  BV: W[n=lr][k=m] = Vh[m][lr]
//  BU: W[n][k=lr] = P*dt * Uh[n][lr]
// bf16 B-frag (m16n8k16 row.col): lane l: b0={W[n][k0],W[n][k0+1]},
//   b1={W[n][k0+8],W[n][k0+9]}; n=8nc+(l>>2), k0=16kc+(l&3)*2.
// ============================================================================
__global__ void koop_frag(const int* __restrict__ steps_p) {
    int steps = steps_p ? *steps_p : 8;
    int P = pick_P(steps);
    const float* AP = (P == 8) ? g_X8 : (P == 4) ? g_X4 : (P == 2) ? g_X2 : g_X;
    float coefU = (float)P * DT_C;

    int id = blockIdx.x * blockDim.x + threadIdx.x;
    if (id >= W_TOTAL / 4) return;

    int r = id & 3, lane = (id >> 2) & 31, rest = id >> 7;
    int tig = lane & 3, lg = lane >> 2;
    int kodd = r >> 1, breg = r & 1;

    float lo, hi;
    if (id < BA_BYTES / 4) {
        int nc = rest & 31, kc2 = rest >> 5;
        int n  = 8 * nc + lg;
        int k0 = 16 * (2 * kc2 + kodd) + tig * 2 + breg * 8;
        lo = AP[n * 256 + k0]     - (n == k0     ? 1.f : 0.f);
        hi = AP[n * 256 + k0 + 1] - (n == k0 + 1 ? 1.f : 0.f);
    } else if (id < (BA_BYTES + BV_BYTES) / 4) {
        int rest2 = rest - (BA_BYTES / 512);
        int nc = rest2 % 12, kc2 = rest2 / 12;
        int n  = 8 * nc + lg;                      // lr index [0,96)
        int k0 = 16 * (2 * kc2 + kodd) + tig * 2 + breg * 8;
        lo = g_Vh[k0 * 96 + n];
        hi = g_Vh[(k0 + 1) * 96 + n];
    } else {
        int rest3 = rest - ((BA_BYTES + BV_BYTES) / 512);
        int nc = rest3 & 31, kc2 = rest3 >> 5;     // kc2 in [0,3)
        int n  = 8 * nc + lg;                      // output col [0,256)
        int k0 = 16 * (2 * kc2 + kodd) + tig * 2 + breg * 8;  // lr [0,96)
        lo = coefU * g_Uh[n * 96 + k0];
        hi = coefU * g_Uh[n * 96 + k0 + 1];
    }
    reinterpret_cast<uint32_t*>(g_wfrag)[id] = packbf(lo, hi);
}

// ============================================================================
// Main persistent kernel: 256 threads, 8 warps x 16 rows, passes = steps/P.
// R14: next-tile L2 prefetch + ldcs/stcs streaming hints.
// ============================================================================
__global__ void __launch_bounds__(256, 1)
koop_main(const float* __restrict__ z_in, const float* __restrict__ a_in,
          const int* __restrict__ steps_p, float* __restrict__ out, int n_tiles) {
    extern __shared__ unsigned char smem[];
    int tid = threadIdx.x, wid = tid >> 5, lane = tid & 31;
    int tig = lane & 3, lg = lane >> 2;

    {
        const uint4* src = reinterpret_cast<const uint4*>(g_wfrag);
        uint4* dst = reinterpret_cast<uint4*>(smem);
        for (int i = tid; i < W_TOTAL / 16; i += 256) dst[i] = src[i];
    }
    __syncthreads();

    const uint32_t sbA = smem_u32(smem) + (uint32_t)lane * 16;
    const uint32_t sbV = sbA + BA_BYTES;
    const uint32_t sbU = sbA + BA_BYTES + BV_BYTES;

    int steps = steps_p ? *steps_p : 8;
    int P = pick_P(steps);
    int passes = (steps > 0) ? steps / P : 0;

    for (int tile = blockIdx.x; tile < n_tiles; tile += gridDim.x) {
        int r0 = tile * TILE_M + wid * 16 + lg;
        const float2* zr0 = reinterpret_cast<const float2*>(z_in + (size_t)r0 * M_DIM);
        const float2* zr1 = reinterpret_cast<const float2*>(z_in + (size_t)(r0 + 8) * M_DIM);

        float acc[32][4];
#pragma unroll
        for (int nc = 0; nc < 32; nc++) {
            float2 v0 = __ldcs(&zr0[4 * nc + tig]);
            float2 v1 = __ldcs(&zr1[4 * nc + tig]);
            acc[nc][0] = v0.x; acc[nc][1] = v0.y;
            acc[nc][2] = v1.x; acc[nc][3] = v1.y;
        }
        float av0[6], av1[6];
#pragma unroll
        for (int l = 0; l < 6; l++) {
            av0[l] = a_in[(size_t)r0 * 6 + l];
            av1[l] = a_in[(size_t)(r0 + 8) * 6 + l];
        }

        // ---- prefetch NEXT tile's z (and a) into L2; ~10us of compute
        //      below gives the DRAM fetch ample time to complete. ----
        {
            int nt = tile + gridDim.x;
            if (nt < n_tiles) {
                int nr = nt * TILE_M + wid * 16;        // this warp's 16 rows
                const char* pb = (const char*)(z_in + (size_t)nr * M_DIM);
#pragma unroll
                for (int q = 0; q < 4; q++)             // 16KB = 128 lines/warp
                    prefetch_l2(pb + (lane + q * 32) * 128);
                if (lane < 3)                           // 16*24B = 3 lines
                    prefetch_l2((const char*)(a_in + (size_t)nr * 6) + lane * 128);
            }
        }

#pragma unroll 1
        for (int s = 0; s < passes; s++) {
            uint32_t af[16][4];
#pragma unroll
            for (int kc = 0; kc < 16; kc++) {
                af[kc][0] = packbf(acc[2 * kc][0],     acc[2 * kc][1]);
                af[kc][1] = packbf(acc[2 * kc][2],     acc[2 * kc][3]);
                af[kc][2] = packbf(acc[2 * kc + 1][0], acc[2 * kc + 1][1]);
                af[kc][3] = packbf(acc[2 * kc + 1][2], acc[2 * kc + 1][3]);
            }

            // ---- A-GEMM: acc += z @ (X^P - I)^T ----
#pragma unroll
            for (int i = 0; i < 256; i++) {
                uint32_t b0, b1, b2, b3;
                lds128(b0, b1, b2, b3, sbA + (uint32_t)i * 512);
                int kc2 = i >> 5, nc = i & 31;
                mma_bf16(acc[nc][0], acc[nc][1], acc[nc][2], acc[nc][3],
                         af[2 * kc2][0], af[2 * kc2][1],
                         af[2 * kc2][2], af[2 * kc2][3], b0, b1);
                mma_bf16(acc[nc][0], acc[nc][1], acc[nc][2], acc[nc][3],
                         af[2 * kc2 + 1][0], af[2 * kc2 + 1][1],
                         af[2 * kc2 + 1][2], af[2 * kc2 + 1][3], b2, b3);
            }

            // ---- V-proj: proj = z @ Vhat^T (N=96), scale by a_l, pack ----
            uint32_t paf[6][4];
#pragma unroll
            for (int ncp = 0; ncp < 6; ncp++) {
                float p0[4] = {0.f, 0.f, 0.f, 0.f};
                float p1[4] = {0.f, 0.f, 0.f, 0.f};
#pragma unroll
                for (int kc2 = 0; kc2 < 8; kc2++) {
                    uint32_t b0, b1, b2, b3;
                    uint32_t base = sbV + (uint32_t)(kc2 * 12 + 2 * ncp) * 512;
                    lds128(b0, b1, b2, b3, base);
                    mma_bf16(p0[0], p0[1], p0[2], p0[3],
                             af[2 * kc2][0], af[2 * kc2][1],
                             af[2 * kc2][2], af[2 * kc2][3], b0, b1);
                    mma_bf16(p0[0], p0[1], p0[2], p0[3],
                             af[2 * kc2 + 1][0], af[2 * kc2 + 1][1],
                             af[2 * kc2 + 1][2], af[2 * kc2 + 1][3], b2, b3);
                    lds128(b0, b1, b2, b3, base + 512);
                    mma_bf16(p1[0], p1[1], p1[2], p1[3],
                             af[2 * kc2][0], af[2 * kc2][1],
                             af[2 * kc2][2], af[2 * kc2][3], b0, b1);
                    mma_bf16(p1[0], p1[1], p1[2], p1[3],
                             af[2 * kc2 + 1][0], af[2 * kc2 + 1][1],
                             af[2 * kc2 + 1][2], af[2 * kc2 + 1][3], b2, b3);
                }
                paf[ncp][0] = packbf(p0[0] * av0[ncp], p0[1] * av0[ncp]);
                paf[ncp][1] = packbf(p0[2] * av1[ncp], p0[3] * av1[ncp]);
                paf[ncp][2] = packbf(p1[0] * av0[ncp], p1[1] * av0[ncp]);
                paf[ncp][3] = packbf(p1[2] * av1[ncp], p1[3] * av1[ncp]);
            }

            // ---- U-GEMM: acc += pa @ (P*dt*Uhat)^T ----
#pragma unroll
            for (int i = 0; i < 96; i++) {
                uint32_t b0, b1, b2, b3;
                lds128(b0, b1, b2, b3, sbU + (uint32_t)i * 512);
                int kc2 = i >> 5, nc = i & 31;
                mma_bf16(acc[nc][0], acc[nc][1], acc[nc][2], acc[nc][3],
                         paf[2 * kc2][0], paf[2 * kc2][1],
                         paf[2 * kc2][2], paf[2 * kc2][3], b0, b1);
                mma_bf16(acc[nc][0], acc[nc][1], acc[nc][2], acc[nc][3],
                         paf[2 * kc2 + 1][0], paf[2 * kc2 + 1][1],
                         paf[2 * kc2 + 1][2], paf[2 * kc2 + 1][3], b2, b3);
            }
        }

        float2* o0 = reinterpret_cast<float2*>(out + (size_t)r0 * M_DIM);
        float2* o1 = reinterpret_cast<float2*>(out + (size_t)(r0 + 8) * M_DIM);
#pragma unroll
        for (int nc = 0; nc < 32; nc++) {
            __stcs(&o0[4 * nc + tig], make_float2(acc[nc][0], acc[nc][1]));
            __stcs(&o1[4 * nc + tig], make_float2(acc[nc][2], acc[nc][3]));
        }
    }
}

// ============================================================================
// kernel_launch — graph-capturable: kernel launches only, no sync, no alloc.
// ============================================================================
extern "C" void kernel_launch(void* const* d_in, const int* in_sizes, int n_in,
                              void* d_out, int out_size) {
    const float* z  = (const float*)d_in[0];
    const float* a  = (const float*)d_in[1];
    const float* A  = (const float*)d_in[2];
    const float* BU = (const float*)d_in[3];
    const float* BV = (const float*)d_in[4];
    const int* steps = (n_in > 5) ? (const int*)d_in[5] : nullptr;

    int n_rows  = in_sizes[0] / M_DIM;
    int n_tiles = n_rows / TILE_M;

    cudaFuncSetAttribute(koop_main, cudaFuncAttributeMaxDynamicSharedMemorySize,
                         W_TOTAL);
    cudaFuncSetAttribute(koop_gemm3, cudaFuncAttributeMaxDynamicSharedMemorySize,
                         G3_SMEM);

    // Precompute levels: {X2, init} -> {X4, T} -> {X8, Uh, Vh} -> frag
    koop_gemm3<<<dim3(8, 8, 2), 256, G3_SMEM>>>(0, A, BU, BV, steps);
    koop_gemm3<<<dim3(8, 8, 2), 256, G3_SMEM>>>(2, A, BU, BV, steps);
    koop_gemm3<<<dim3(8, 8, 3), 256, G3_SMEM>>>(4, A, BU, BV, steps);
    koop_frag<<<(W_TOTAL / 4 + 255) / 256, 256>>>(steps);

    int dev = 0, sm_count = 0;
    cudaGetDevice(&dev);
    cudaDeviceGetAttribute(&sm_count, cudaDevAttrMultiProcessorCount, dev);
    if (sm_count <= 0) sm_count = 148;
    int grid = n_tiles < sm_count ? n_tiles : sm_count;

    koop_main<<<grid, 256, W_TOTAL>>>(z, a, steps, (float*)d_out, n_tiles);
}

// round 15
// speedup vs baseline: 1.0871x; 1.0362x over previous
#include <cuda_runtime.h>
#include <cuda_bf16.h>
#include <cstdint>

// ============================================================================
// KoopmanOperator: z_{t+1} = z + DT*(z@A^T + sum_l a_l * U_l (V_l^T z))
// N=262144 rows, m=256, da=6, r=16, steps=8.
//
// R15 = R14 (246us) with the ENTIRE pipeline fused into ONE persistent
// kernel. Levels separated by a sense-reversing device-wide spin barrier
// (safe: 229KB SMEM -> 1 CTA/SM, grid = sm_count -> all CTAs co-resident;
// barrier self-resets across graph replays, no memset needed).
//   P0: X2 = X*X (xform on the fly) + init(g_X, Um, Vm)
//   P1: X4 = X2*X2 ; T = X2^T*Vm
//   P2: X8 = X4*X4 ; Uh = E1*Um ; Vh = X^T*T
//   P3: fragment images -> g_wfrag
//   P4: copy g_wfrag -> SMEM, run fused-operator main loop (unchanged R14)
// First z tiles L2-prefetched during precompute.
//
// Fusion: z_out = (X + dt B)^P z ≈ X^P z + P*dt*(X^{P/2} U)(V^T X^{P-1-P/2}) z
// with X = I + dt*A; steps=8 -> P=8, one pass. Hot loop: mma.sync bf16,
// z = fp32 D-fragment accumulator (identity exact).
// ============================================================================

#define DT_C    0.1f
#define BMAX_C  0.3f

static constexpr int M_DIM  = 256;
static constexpr int TILE_M = 128;   // rows per CTA (8 warps x 16)

static constexpr int BA_BYTES = 8 * 32 * 512;   // X^P - I
static constexpr int BV_BYTES = 8 * 12 * 512;   // Vhat
static constexpr int BU_BYTES = 3 * 32 * 512;   // P*dt*Uhat
static constexpr int W_TOTAL  = BA_BYTES + BV_BYTES + BU_BYTES;  // 229376

__device__ __align__(16) unsigned char g_wfrag[W_TOTAL];

// fp32 precompute scratch
__device__ __align__(16) float g_X [65536];
__device__ __align__(16) float g_X2[65536];
__device__ __align__(16) float g_X4[65536];
__device__ __align__(16) float g_X8[65536];
__device__ __align__(16) float g_Um[24576];   // [m][lr]
__device__ __align__(16) float g_Vm[24576];   // [m][lr]
__device__ __align__(16) float g_T [24576];   // [m][lr]  X2^T * Vm (P=8)
__device__ __align__(16) float g_Uh[24576];   // [m][lr]  E1 * Um
__device__ __align__(16) float g_Vh[24576];   // [m][lr]  E2^T * Vm

// sense-reversing grid barrier state (self-resetting; zero-init at load)
__device__ unsigned g_bcount = 0;
__device__ unsigned g_bgen   = 0;

__device__ __forceinline__ int pick_P(int steps) {
    if (steps > 0 && (steps % 8) == 0) return 8;
    if (steps > 0 && (steps % 4) == 0) return 4;
    if (steps > 0 && (steps % 2) == 0) return 2;
    return 1;
}

// ============================================================================
// helpers
// ============================================================================
__device__ __forceinline__ uint32_t smem_u32(const void* p) {
    uint32_t a;
    asm("{ .reg .u64 t; cvta.to.shared.u64 t, %1; cvt.u32.u64 %0, t; }"
        : "=r"(a) : "l"(p));
    return a;
}

// pack bf16x2: lo -> low 16 bits (first PTX src -> HIGH half).
__device__ __forceinline__ uint32_t packbf(float lo, float hi) {
    uint32_t r;
    asm("cvt.rn.satfinite.bf16x2.f32 %0, %1, %2;" : "=r"(r) : "f"(hi), "f"(lo));
    return r;
}

__device__ __forceinline__ void lds128(uint32_t& x, uint32_t& y,
                                       uint32_t& z, uint32_t& w, uint32_t addr) {
    asm volatile("ld.shared.v4.b32 {%0,%1,%2,%3}, [%4];"
                 : "=r"(x), "=r"(y), "=r"(z), "=r"(w) : "r"(addr));
}

__device__ __forceinline__ void mma_bf16(float& d0, float& d1, float& d2, float& d3,
                                         uint32_t a0, uint32_t a1, uint32_t a2,
                                         uint32_t a3, uint32_t b0, uint32_t b1) {
    asm volatile(
        "mma.sync.aligned.m16n8k16.row.col.f32.bf16.bf16.f32 "
        "{%0,%1,%2,%3}, {%4,%5,%6,%7}, {%8,%9}, {%0,%1,%2,%3};"
        : "+f"(d0), "+f"(d1), "+f"(d2), "+f"(d3)
        : "r"(a0), "r"(a1), "r"(a2), "r"(a3), "r"(b0), "r"(b1));
}

__device__ __forceinline__ void prefetch_l2(const void* p) {
    asm volatile("prefetch.global.L2 [%0];" :: "l"(p));
}

// Grid-wide barrier. Requires all gridDim.x CTAs co-resident (1 CTA/SM,
// grid <= sm_count). Sense-reversing: count self-resets, gen monotonic.
__device__ __forceinline__ void grid_barrier(unsigned G) {
    __syncthreads();
    if (threadIdx.x == 0) {
        __threadfence();
        unsigned g = *(volatile unsigned*)&g_bgen;
        unsigned t = atomicAdd(&g_bcount, 1u);
        if (t == G - 1u) {
            atomicExch(&g_bcount, 0u);
            __threadfence();
            atomicAdd(&g_bgen, 1u);
        } else {
            while (*(volatile unsigned*)&g_bgen == g) __nanosleep(64);
        }
        __threadfence();
    }
    __syncthreads();
}

// ============================================================================
// GEMM tile (device fn): C[256,N] 32x32 tile = op(A)[256,256] * B[256,N].
// Full 32x256 A-slab + 256x32 B-slab staged in SMEM, one sync, straight k.
// ============================================================================
static constexpr int AS_PITCH = 260;
static constexpr int BS_PITCH = 36;

__device__ void gemm_tile(const float* __restrict__ Ap,
                          const float* __restrict__ Bp, float* __restrict__ Cp,
                          int N, bool tA, bool xform, int row0, int col0,
                          float* sm3) {
    int tid = threadIdx.x;
    float* As = sm3;                    // [32][AS_PITCH]
    float* Bs = sm3 + 32 * AS_PITCH;    // [256][BS_PITCH]

    if (!tA) {
        for (int q = tid; q < 2048; q += 256) {
            int i = q >> 6, kk = (q & 63) * 4;
            float4 v = *reinterpret_cast<const float4*>(Ap + (row0 + i) * 256 + kk);
            if (xform) {
                int rr = row0 + i;
                v.x = DT_C * v.x + (rr == kk     ? 1.f : 0.f);
                v.y = DT_C * v.y + (rr == kk + 1 ? 1.f : 0.f);
                v.z = DT_C * v.z + (rr == kk + 2 ? 1.f : 0.f);
                v.w = DT_C * v.w + (rr == kk + 3 ? 1.f : 0.f);
            }
            *reinterpret_cast<float4*>(As + i * AS_PITCH + kk) = v;
        }
    } else {
        for (int q = tid; q < 2048; q += 256) {
            int k = q >> 3, ii = (q & 7) * 4;
            float4 v = *reinterpret_cast<const float4*>(Ap + k * 256 + row0 + ii);
            As[(ii + 0) * AS_PITCH + k] = v.x;
            As[(ii + 1) * AS_PITCH + k] = v.y;
            As[(ii + 2) * AS_PITCH + k] = v.z;
            As[(ii + 3) * AS_PITCH + k] = v.w;
        }
    }
    for (int q = tid; q < 2048; q += 256) {
        int k = q >> 3, jj = (q & 7) * 4;
        float4 v = *reinterpret_cast<const float4*>(Bp + k * N + col0 + jj);
        if (xform) {
            int cc = col0 + jj;
            v.x = DT_C * v.x + (k == cc     ? 1.f : 0.f);
            v.y = DT_C * v.y + (k == cc + 1 ? 1.f : 0.f);
            v.z = DT_C * v.z + (k == cc + 2 ? 1.f : 0.f);
            v.w = DT_C * v.w + (k == cc + 3 ? 1.f : 0.f);
        }
        *reinterpret_cast<float4*>(Bs + k * BS_PITCH + jj) = v;
    }
    __syncthreads();

    int tx = tid & 15, ty = tid >> 4;
    const float* ar0 = As + (ty * 2) * AS_PITCH;
    const float* ar1 = ar0 + AS_PITCH;
    float c00 = 0.f, c01 = 0.f, c10 = 0.f, c11 = 0.f;
#pragma unroll 8
    for (int k = 0; k < 256; k++) {
        float2 b = *reinterpret_cast<const float2*>(Bs + k * BS_PITCH + tx * 2);
        float a0 = ar0[k], a1 = ar1[k];
        c00 += a0 * b.x; c01 += a0 * b.y;
        c10 += a1 * b.x; c11 += a1 * b.y;
    }
    int rr = row0 + ty * 2, cc = col0 + tx * 2;
    Cp[rr * N + cc] = c00;       Cp[rr * N + cc + 1] = c01;
    Cp[(rr + 1) * N + cc] = c10; Cp[(rr + 1) * N + cc + 1] = c11;
    __syncthreads();            // protect As/Bs before next item reuses them
}

__device__ void copy_tile(const float* __restrict__ Bp, float* __restrict__ Cp,
                          int N, int row0, int col0) {
    for (int q = threadIdx.x; q < 32 * 32; q += 256) {
        int i = q >> 5, j = q & 31;
        Cp[(row0 + i) * N + col0 + j] = Bp[(row0 + i) * N + col0 + j];
    }
}

// ============================================================================
// THE kernel: precompute levels + barriers + main loop.
// ============================================================================
__global__ void __launch_bounds__(256, 1)
koop_all(const float* __restrict__ z_in, const float* __restrict__ a_in,
         const float* __restrict__ Araw, const float* __restrict__ BUraw,
         const float* __restrict__ BVraw, const int* __restrict__ steps_p,
         float* __restrict__ out, int n_tiles) {
    extern __shared__ unsigned char smem[];
    float* sm3 = reinterpret_cast<float*>(smem);
    const unsigned G = gridDim.x;
    int tid = threadIdx.x, wid = tid >> 5, lane = tid & 31;
    int tig = lane & 3, lg = lane >> 2;

    int steps = steps_p ? *steps_p : 8;
    int P = pick_P(steps);
    int passes = (steps > 0) ? steps / P : 0;

    // ---- warm L2 with this CTA's first z tile (needed ~15us from now) ----
    if ((int)blockIdx.x < n_tiles) {
        const char* pz = (const char*)(z_in + (size_t)blockIdx.x * TILE_M * M_DIM);
#pragma unroll
        for (int q = 0; q < 4; q++) prefetch_l2(pz + (tid + q * 256) * 128);
    }

    // ================= P0: X2 = X*X (xform) + init =================
    for (int it = blockIdx.x; it < 128; it += G) {
        if (it < 64) {
            gemm_tile(Araw, Araw, g_X2, 256, false, true,
                      (it >> 3) * 32, (it & 7) * 32, sm3);
        } else {
            int c = it - 64;
            for (int i = tid; i < 1024; i += 256) {
                int id = c * 1024 + i;
                int n = id >> 8, k = id & 255;
                g_X[id] = DT_C * Araw[id] + (n == k ? 1.f : 0.f);
            }
            for (int i = tid; i < 384; i += 256) {
                int id = c * 384 + i;
                int m = id / 96, lr = id % 96, l = lr >> 4, ri = lr & 15;
                g_Um[id] = tanhf(BUraw[(l * 256 + m) * 16 + ri]) * BMAX_C;
                g_Vm[id] = tanhf(BVraw[(l * 256 + m) * 16 + ri]) * BMAX_C;
            }
        }
    }
    grid_barrier(G);

    // ================= P1: X4 = X2*X2 ; T = X2^T*Vm =================
    for (int it = blockIdx.x; it < 88; it += G) {
        if (it < 64) {
            gemm_tile(g_X2, g_X2, g_X4, 256, false, false,
                      (it >> 3) * 32, (it & 7) * 32, sm3);
        } else {
            int t = it - 64;                    // 24 tiles: 8 rows x 3 cols
            int r0 = (t / 3) * 32, c0 = (t % 3) * 32;
            if (P == 8) gemm_tile(g_X2, g_Vm, g_T, 96, true, false, r0, c0, sm3);
            else        copy_tile(g_Vm, g_T, 96, r0, c0);
        }
    }
    grid_barrier(G);

    // ============ P2: X8 = X4*X4 ; Uh = E1*Um ; Vh = X^T*T ============
    for (int it = blockIdx.x; it < 112; it += G) {
        if (it < 64) {
            gemm_tile(g_X4, g_X4, g_X8, 256, false, false,
                      (it >> 3) * 32, (it & 7) * 32, sm3);
        } else if (it < 88) {
            int t = it - 64;
            int r0 = (t / 3) * 32, c0 = (t % 3) * 32;
            if      (P == 8) gemm_tile(g_X4, g_Um, g_Uh, 96, false, false, r0, c0, sm3);
            else if (P == 4) gemm_tile(g_X2, g_Um, g_Uh, 96, false, false, r0, c0, sm3);
            else if (P == 2) gemm_tile(g_X,  g_Um, g_Uh, 96, false, false, r0, c0, sm3);
            else             copy_tile(g_Um, g_Uh, 96, r0, c0);
        } else {
            int t = it - 88;
            int r0 = (t / 3) * 32, c0 = (t % 3) * 32;
            if (P >= 4) gemm_tile(g_X, g_T, g_Vh, 96, true, false, r0, c0, sm3);
            else        copy_tile(g_T, g_Vh, 96, r0, c0);
        }
    }
    grid_barrier(G);

    // ================= P3: fragment images -> g_wfrag =================
    {
        const float* AP = (P == 8) ? g_X8 : (P == 4) ? g_X4
                        : (P == 2) ? g_X2 : g_X;
        float coefU = (float)P * DT_C;
        for (int id = blockIdx.x * 256 + tid; id < W_TOTAL / 4; id += G * 256) {
            int r = id & 3, ln = (id >> 2) & 31, rest = id >> 7;
            int tg = ln & 3, lgr = ln >> 2;
            int kodd = r >> 1, breg = r & 1;
            float lo, hi;
            if (id < BA_BYTES / 4) {
                int nc = rest & 31, kc2 = rest >> 5;
                int n  = 8 * nc + lgr;
                int k0 = 16 * (2 * kc2 + kodd) + tg * 2 + breg * 8;
                lo = AP[n * 256 + k0]     - (n == k0     ? 1.f : 0.f);
                hi = AP[n * 256 + k0 + 1] - (n == k0 + 1 ? 1.f : 0.f);
            } else if (id < (BA_BYTES + BV_BYTES) / 4) {
                int rest2 = rest - (BA_BYTES / 512);
                int nc = rest2 % 12, kc2 = rest2 / 12;
                int n  = 8 * nc + lgr;
                int k0 = 16 * (2 * kc2 + kodd) + tg * 2 + breg * 8;
                lo = g_Vh[k0 * 96 + n];
                hi = g_Vh[(k0 + 1) * 96 + n];
            } else {
                int rest3 = rest - ((BA_BYTES + BV_BYTES) / 512);
                int nc = rest3 & 31, kc2 = rest3 >> 5;
                int n  = 8 * nc + lgr;
                int k0 = 16 * (2 * kc2 + kodd) + tg * 2 + breg * 8;
                lo = coefU * g_Uh[n * 96 + k0];
                hi = coefU * g_Uh[n * 96 + k0 + 1];
            }
            reinterpret_cast<uint32_t*>(g_wfrag)[id] = packbf(lo, hi);
        }
    }
    grid_barrier(G);

    // ================= P4: weights -> SMEM, main loop =================
    {
        const uint4* src = reinterpret_cast<const uint4*>(g_wfrag);
        uint4* dst = reinterpret_cast<uint4*>(smem);
        for (int i = tid; i < W_TOTAL / 16; i += 256) dst[i] = src[i];
    }
    __syncthreads();

    const uint32_t sbA = smem_u32(smem) + (uint32_t)lane * 16;
    const uint32_t sbV = sbA + BA_BYTES;
    const uint32_t sbU = sbA + BA_BYTES + BV_BYTES;

    for (int tile = blockIdx.x; tile < n_tiles; tile += gridDim.x) {
        int r0 = tile * TILE_M + wid * 16 + lg;
        const float2* zr0 = reinterpret_cast<const float2*>(z_in + (size_t)r0 * M_DIM);
        const float2* zr1 = reinterpret_cast<const float2*>(z_in + (size_t)(r0 + 8) * M_DIM);

        float acc[32][4];
#pragma unroll
        for (int nc = 0; nc < 32; nc++) {
            float2 v0 = __ldcs(&zr0[4 * nc + tig]);
            float2 v1 = __ldcs(&zr1[4 * nc + tig]);
            acc[nc][0] = v0.x; acc[nc][1] = v0.y;
            acc[nc][2] = v1.x; acc[nc][3] = v1.y;
        }
        float av0[6], av1[6];
#pragma unroll
        for (int l = 0; l < 6; l++) {
            av0[l] = a_in[(size_t)r0 * 6 + l];
            av1[l] = a_in[(size_t)(r0 + 8) * 6 + l];
        }

        // prefetch NEXT tile's z (and a) into L2 under this tile's compute
        {
            int nt = tile + gridDim.x;
            if (nt < n_tiles) {
                int nr = nt * TILE_M + wid * 16;
                const char* pb = (const char*)(z_in + (size_t)nr * M_DIM);
#pragma unroll
                for (int q = 0; q < 4; q++)
                    prefetch_l2(pb + (lane + q * 32) * 128);
                if (lane < 3)
                    prefetch_l2((const char*)(a_in + (size_t)nr * 6) + lane * 128);
            }
        }

#pragma unroll 1
        for (int s = 0; s < passes; s++) {
            uint32_t af[16][4];
#pragma unroll
            for (int kc = 0; kc < 16; kc++) {
                af[kc][0] = packbf(acc[2 * kc][0],     acc[2 * kc][1]);
                af[kc][1] = packbf(acc[2 * kc][2],     acc[2 * kc][3]);
                af[kc][2] = packbf(acc[2 * kc + 1][0], acc[2 * kc + 1][1]);
                af[kc][3] = packbf(acc[2 * kc + 1][2], acc[2 * kc + 1][3]);
            }

            // ---- A-GEMM: acc += z @ (X^P - I)^T ----
#pragma unroll
            for (int i = 0; i < 256; i++) {
                uint32_t b0, b1, b2, b3;
                lds128(b0, b1, b2, b3, sbA + (uint32_t)i * 512);
                int kc2 = i >> 5, nc = i & 31;
                mma_bf16(acc[nc][0], acc[nc][1], acc[nc][2], acc[nc][3],
                         af[2 * kc2][0], af[2 * kc2][1],
                         af[2 * kc2][2], af[2 * kc2][3], b0, b1);
                mma_bf16(acc[nc][0], acc[nc][1], acc[nc][2], acc[nc][3],
                         af[2 * kc2 + 1][0], af[2 * kc2 + 1][1],
                         af[2 * kc2 + 1][2], af[2 * kc2 + 1][3], b2, b3);
            }

            // ---- V-proj: proj = z @ Vhat^T (N=96), scale by a_l, pack ----
            uint32_t paf[6][4];
#pragma unroll
            for (int ncp = 0; ncp < 6; ncp++) {
                float p0[4] = {0.f, 0.f, 0.f, 0.f};
                float p1[4] = {0.f, 0.f, 0.f, 0.f};
#pragma unroll
                for (int kc2 = 0; kc2 < 8; kc2++) {
                    uint32_t b0, b1, b2, b3;
                    uint32_t base = sbV + (uint32_t)(kc2 * 12 + 2 * ncp) * 512;
                    lds128(b0, b1, b2, b3, base);
                    mma_bf16(p0[0], p0[1], p0[2], p0[3],
                             af[2 * kc2][0], af[2 * kc2][1],
                             af[2 * kc2][2], af[2 * kc2][3], b0, b1);
                    mma_bf16(p0[0], p0[1], p0[2], p0[3],
                             af[2 * kc2 + 1][0], af[2 * kc2 + 1][1],
                             af[2 * kc2 + 1][2], af[2 * kc2 + 1][3], b2, b3);
                    lds128(b0, b1, b2, b3, base + 512);
                    mma_bf16(p1[0], p1[1], p1[2], p1[3],
                             af[2 * kc2][0], af[2 * kc2][1],
                             af[2 * kc2][2], af[2 * kc2][3], b0, b1);
                    mma_bf16(p1[0], p1[1], p1[2], p1[3],
                             af[2 * kc2 + 1][0], af[2 * kc2 + 1][1],
                             af[2 * kc2 + 1][2], af[2 * kc2 + 1][3], b2, b3);
                }
                paf[ncp][0] = packbf(p0[0] * av0[ncp], p0[1] * av0[ncp]);
                paf[ncp][1] = packbf(p0[2] * av1[ncp], p0[3] * av1[ncp]);
                paf[ncp][2] = packbf(p1[0] * av0[ncp], p1[1] * av0[ncp]);
                paf[ncp][3] = packbf(p1[2] * av1[ncp], p1[3] * av1[ncp]);
            }

            // ---- U-GEMM: acc += pa @ (P*dt*Uhat)^T ----
#pragma unroll
            for (int i = 0; i < 96; i++) {
                uint32_t b0, b1, b2, b3;
                lds128(b0, b1, b2, b3, sbU + (uint32_t)i * 512);
                int kc2 = i >> 5, nc = i & 31;
                mma_bf16(acc[nc][0], acc[nc][1], acc[nc][2], acc[nc][3],
                         paf[2 * kc2][0], paf[2 * kc2][1],
                         paf[2 * kc2][2], paf[2 * kc2][3], b0, b1);
                mma_bf16(acc[nc][0], acc[nc][1], acc[nc][2], acc[nc][3],
                         paf[2 * kc2 + 1][0], paf[2 * kc2 + 1][1],
                         paf[2 * kc2 + 1][2], paf[2 * kc2 + 1][3], b2, b3);
            }
        }

        float2* o0 = reinterpret_cast<float2*>(out + (size_t)r0 * M_DIM);
        float2* o1 = reinterpret_cast<float2*>(out + (size_t)(r0 + 8) * M_DIM);
#pragma unroll
        for (int nc = 0; nc < 32; nc++) {
            __stcs(&o0[4 * nc + tig], make_float2(acc[nc][0], acc[nc][1]));
            __stcs(&o1[4 * nc + tig], make_float2(acc[nc][2], acc[nc][3]));
        }
    }
}

// ============================================================================
// kernel_launch — graph-capturable: ONE kernel launch, no sync, no alloc.
// ============================================================================
extern "C" void kernel_launch(void* const* d_in, const int* in_sizes, int n_in,
                              void* d_out, int out_size) {
    const float* z  = (const float*)d_in[0];
    const float* a  = (const float*)d_in[1];
    const float* A  = (const float*)d_in[2];
    const float* BU = (const float*)d_in[3];
    const float* BV = (const float*)d_in[4];
    const int* steps = (n_in > 5) ? (const int*)d_in[5] : nullptr;

    int n_rows  = in_sizes[0] / M_DIM;
    int n_tiles = n_rows / TILE_M;

    cudaFuncSetAttribute(koop_all, cudaFuncAttributeMaxDynamicSharedMemorySize,
                         W_TOTAL);

    int dev = 0, sm_count = 0;
    cudaGetDevice(&dev);
    cudaDeviceGetAttribute(&sm_count, cudaDevAttrMultiProcessorCount, dev);
    if (sm_count <= 0) sm_count = 148;
    // 229KB SMEM -> exactly 1 CTA/SM; grid = sm_count guarantees all CTAs
    // co-resident, which the grid barrier requires.
    int grid = sm_count;

    koop_all<<<grid, 256, W_TOTAL>>>(z, a, A, BU, BV, steps,
                                     (float*)d_out, n_tiles);
}

// round 16
// speedup vs baseline: 1.1118x; 1.0227x over previous
#include <cuda_runtime.h>
#include <cuda_bf16.h>
#include <cstdint>

// ============================================================================
// KoopmanOperator: z_{t+1} = z + DT*(z@A^T + sum_l a_l * U_l (V_l^T z))
// N=262144 rows, m=256, da=6, r=16, steps=8.
//
// R16 = R15 (237.6us, single fused persistent kernel) + tail balancing:
//  * uniform 13 rounds of full tiles (1976) then the 72 remaining tiles run
//    as 144 half-tiles (64 rows, warps 0-3 = one warp/SMSP) across 144 CTAs
//    instead of 72 full tiles on 72 CTAs with 80 SMs idle.
//  * barrier nanosleep 64 -> 32.
//
// Pipeline (one launch, grid-wide sense-reversing barrier between levels;
// safe: 229KB SMEM -> 1 CTA/SM, grid = sm_count -> all co-resident):
//   P0: X2 = X*X (xform on the fly) + init(g_X, Um, Vm)
//   P1: X4 = X2*X2 ; T = X2^T*Vm
//   P2: X8 = X4*X4 ; Uh = E1*Um ; Vh = X^T*T
//   P3: fragment images -> g_wfrag
//   P4: weights -> SMEM, fused-operator main loop
//
// Fusion: z_out = (X + dt B)^P z ≈ X^P z + P*dt*(X^{P/2} U)(V^T X^{P-1-P/2}) z
// with X = I + dt*A; steps=8 -> P=8, one pass. Hot loop: mma.sync bf16,
// z = fp32 D-fragment accumulator (identity exact).
// ============================================================================

#define DT_C    0.1f
#define BMAX_C  0.3f

static constexpr int M_DIM  = 256;
static constexpr int TILE_M = 128;   // rows per CTA (8 warps x 16)

static constexpr int BA_BYTES = 8 * 32 * 512;   // X^P - I
static constexpr int BV_BYTES = 8 * 12 * 512;   // Vhat
static constexpr int BU_BYTES = 3 * 32 * 512;   // P*dt*Uhat
static constexpr int W_TOTAL  = BA_BYTES + BV_BYTES + BU_BYTES;  // 229376

__device__ __align__(16) unsigned char g_wfrag[W_TOTAL];

// fp32 precompute scratch
__device__ __align__(16) float g_X [65536];
__device__ __align__(16) float g_X2[65536];
__device__ __align__(16) float g_X4[65536];
__device__ __align__(16) float g_X8[65536];
__device__ __align__(16) float g_Um[24576];   // [m][lr]
__device__ __align__(16) float g_Vm[24576];   // [m][lr]
__device__ __align__(16) float g_T [24576];   // [m][lr]  X2^T * Vm (P=8)
__device__ __align__(16) float g_Uh[24576];   // [m][lr]  E1 * Um
__device__ __align__(16) float g_Vh[24576];   // [m][lr]  E2^T * Vm

// sense-reversing grid barrier state (self-resetting; zero-init at load)
__device__ unsigned g_bcount = 0;
__device__ unsigned g_bgen   = 0;

__device__ __forceinline__ int pick_P(int steps) {
    if (steps > 0 && (steps % 8) == 0) return 8;
    if (steps > 0 && (steps % 4) == 0) return 4;
    if (steps > 0 && (steps % 2) == 0) return 2;
    return 1;
}

// ============================================================================
// helpers
// ============================================================================
__device__ __forceinline__ uint32_t smem_u32(const void* p) {
    uint32_t a;
    asm("{ .reg .u64 t; cvta.to.shared.u64 t, %1; cvt.u32.u64 %0, t; }"
        : "=r"(a) : "l"(p));
    return a;
}

// pack bf16x2: lo -> low 16 bits (first PTX src -> HIGH half).
__device__ __forceinline__ uint32_t packbf(float lo, float hi) {
    uint32_t r;
    asm("cvt.rn.satfinite.bf16x2.f32 %0, %1, %2;" : "=r"(r) : "f"(hi), "f"(lo));
    return r;
}

__device__ __forceinline__ void lds128(uint32_t& x, uint32_t& y,
                                       uint32_t& z, uint32_t& w, uint32_t addr) {
    asm volatile("ld.shared.v4.b32 {%0,%1,%2,%3}, [%4];"
                 : "=r"(x), "=r"(y), "=r"(z), "=r"(w) : "r"(addr));
}

__device__ __forceinline__ void mma_bf16(float& d0, float& d1, float& d2, float& d3,
                                         uint32_t a0, uint32_t a1, uint32_t a2,
                                         uint32_t a3, uint32_t b0, uint32_t b1) {
    asm volatile(
        "mma.sync.aligned.m16n8k16.row.col.f32.bf16.bf16.f32 "
        "{%0,%1,%2,%3}, {%4,%5,%6,%7}, {%8,%9}, {%0,%1,%2,%3};"
        : "+f"(d0), "+f"(d1), "+f"(d2), "+f"(d3)
        : "r"(a0), "r"(a1), "r"(a2), "r"(a3), "r"(b0), "r"(b1));
}

__device__ __forceinline__ void prefetch_l2(const void* p) {
    asm volatile("prefetch.global.L2 [%0];" :: "l"(p));
}

// Grid-wide barrier. Requires all gridDim.x CTAs co-resident.
__device__ __forceinline__ void grid_barrier(unsigned G) {
    __syncthreads();
    if (threadIdx.x == 0) {
        __threadfence();
        unsigned g = *(volatile unsigned*)&g_bgen;
        unsigned t = atomicAdd(&g_bcount, 1u);
        if (t == G - 1u) {
            atomicExch(&g_bcount, 0u);
            __threadfence();
            atomicAdd(&g_bgen, 1u);
        } else {
            while (*(volatile unsigned*)&g_bgen == g) __nanosleep(32);
        }
        __threadfence();
    }
    __syncthreads();
}

// ============================================================================
// GEMM tile (device fn): C[256,N] 32x32 tile = op(A)[256,256] * B[256,N].
// ============================================================================
static constexpr int AS_PITCH = 260;
static constexpr int BS_PITCH = 36;

__device__ void gemm_tile(const float* __restrict__ Ap,
                          const float* __restrict__ Bp, float* __restrict__ Cp,
                          int N, bool tA, bool xform, int row0, int col0,
                          float* sm3) {
    int tid = threadIdx.x;
    float* As = sm3;                    // [32][AS_PITCH]
    float* Bs = sm3 + 32 * AS_PITCH;    // [256][BS_PITCH]

    if (!tA) {
        for (int q = tid; q < 2048; q += 256) {
            int i = q >> 6, kk = (q & 63) * 4;
            float4 v = *reinterpret_cast<const float4*>(Ap + (row0 + i) * 256 + kk);
            if (xform) {
                int rr = row0 + i;
                v.x = DT_C * v.x + (rr == kk     ? 1.f : 0.f);
                v.y = DT_C * v.y + (rr == kk + 1 ? 1.f : 0.f);
                v.z = DT_C * v.z + (rr == kk + 2 ? 1.f : 0.f);
                v.w = DT_C * v.w + (rr == kk + 3 ? 1.f : 0.f);
            }
            *reinterpret_cast<float4*>(As + i * AS_PITCH + kk) = v;
        }
    } else {
        for (int q = tid; q < 2048; q += 256) {
            int k = q >> 3, ii = (q & 7) * 4;
            float4 v = *reinterpret_cast<const float4*>(Ap + k * 256 + row0 + ii);
            As[(ii + 0) * AS_PITCH + k] = v.x;
            As[(ii + 1) * AS_PITCH + k] = v.y;
            As[(ii + 2) * AS_PITCH + k] = v.z;
            As[(ii + 3) * AS_PITCH + k] = v.w;
        }
    }
    for (int q = tid; q < 2048; q += 256) {
        int k = q >> 3, jj = (q & 7) * 4;
        float4 v = *reinterpret_cast<const float4*>(Bp + k * N + col0 + jj);
        if (xform) {
            int cc = col0 + jj;
            v.x = DT_C * v.x + (k == cc     ? 1.f : 0.f);
            v.y = DT_C * v.y + (k == cc + 1 ? 1.f : 0.f);
            v.z = DT_C * v.z + (k == cc + 2 ? 1.f : 0.f);
            v.w = DT_C * v.w + (k == cc + 3 ? 1.f : 0.f);
        }
        *reinterpret_cast<float4*>(Bs + k * BS_PITCH + jj) = v;
    }
    __syncthreads();

    int tx = tid & 15, ty = tid >> 4;
    const float* ar0 = As + (ty * 2) * AS_PITCH;
    const float* ar1 = ar0 + AS_PITCH;
    float c00 = 0.f, c01 = 0.f, c10 = 0.f, c11 = 0.f;
#pragma unroll 8
    for (int k = 0; k < 256; k++) {
        float2 b = *reinterpret_cast<const float2*>(Bs + k * BS_PITCH + tx * 2);
        float a0 = ar0[k], a1 = ar1[k];
        c00 += a0 * b.x; c01 += a0 * b.y;
        c10 += a1 * b.x; c11 += a1 * b.y;
    }
    int rr = row0 + ty * 2, cc = col0 + tx * 2;
    Cp[rr * N + cc] = c00;       Cp[rr * N + cc + 1] = c01;
    Cp[(rr + 1) * N + cc] = c10; Cp[(rr + 1) * N + cc + 1] = c11;
    __syncthreads();            // protect As/Bs before next item reuses them
}

__device__ void copy_tile(const float* __restrict__ Bp, float* __restrict__ Cp,
                          int N, int row0, int col0) {
    for (int q = threadIdx.x; q < 32 * 32; q += 256) {
        int i = q >> 5, j = q & 31;
        Cp[(row0 + i) * N + col0 + j] = Bp[(row0 + i) * N + col0 + j];
    }
}

// ============================================================================
// One z row-group (16 rows this warp, r0 = first-row-of-pair for this thread).
// pf_row >= 0: also L2-prefetch that (future) row-group's z + a.
// NO CTA-level sync inside -> safe to call from a subset of warps.
// ============================================================================
__device__ __forceinline__ void koop_tile(
    const float* __restrict__ z_in, const float* __restrict__ a_in,
    float* __restrict__ out, int r0, int pf_row,
    uint32_t sbA, uint32_t sbV, uint32_t sbU,
    int passes, int tig, int lane)
{
    const float2* zr0 = reinterpret_cast<const float2*>(z_in + (size_t)r0 * M_DIM);
    const float2* zr1 = reinterpret_cast<const float2*>(z_in + (size_t)(r0 + 8) * M_DIM);

    float acc[32][4];
#pragma unroll
    for (int nc = 0; nc < 32; nc++) {
        float2 v0 = __ldcs(&zr0[4 * nc + tig]);
        float2 v1 = __ldcs(&zr1[4 * nc + tig]);
        acc[nc][0] = v0.x; acc[nc][1] = v0.y;
        acc[nc][2] = v1.x; acc[nc][3] = v1.y;
    }
    float av0[6], av1[6];
#pragma unroll
    for (int l = 0; l < 6; l++) {
        av0[l] = a_in[(size_t)r0 * 6 + l];
        av1[l] = a_in[(size_t)(r0 + 8) * 6 + l];
    }

    if (pf_row >= 0) {
        const char* pb = (const char*)(z_in + (size_t)pf_row * M_DIM);
#pragma unroll
        for (int q = 0; q < 4; q++)
            prefetch_l2(pb + (lane + q * 32) * 128);
        if (lane < 3)
            prefetch_l2((const char*)(a_in + (size_t)pf_row * 6) + lane * 128);
    }

#pragma unroll 1
    for (int s = 0; s < passes; s++) {
        uint32_t af[16][4];
#pragma unroll
        for (int kc = 0; kc < 16; kc++) {
            af[kc][0] = packbf(acc[2 * kc][0],     acc[2 * kc][1]);
            af[kc][1] = packbf(acc[2 * kc][2],     acc[2 * kc][3]);
            af[kc][2] = packbf(acc[2 * kc + 1][0], acc[2 * kc + 1][1]);
            af[kc][3] = packbf(acc[2 * kc + 1][2], acc[2 * kc + 1][3]);
        }

        // ---- A-GEMM: acc += z @ (X^P - I)^T ----
#pragma unroll
        for (int i = 0; i < 256; i++) {
            uint32_t b0, b1, b2, b3;
            lds128(b0, b1, b2, b3, sbA + (uint32_t)i * 512);
            int kc2 = i >> 5, nc = i & 31;
            mma_bf16(acc[nc][0], acc[nc][1], acc[nc][2], acc[nc][3],
                     af[2 * kc2][0], af[2 * kc2][1],
                     af[2 * kc2][2], af[2 * kc2][3], b0, b1);
            mma_bf16(acc[nc][0], acc[nc][1], acc[nc][2], acc[nc][3],
                     af[2 * kc2 + 1][0], af[2 * kc2 + 1][1],
                     af[2 * kc2 + 1][2], af[2 * kc2 + 1][3], b2, b3);
        }

        // ---- V-proj: proj = z @ Vhat^T (N=96), scale by a_l, pack ----
        uint32_t paf[6][4];
#pragma unroll
        for (int ncp = 0; ncp < 6; ncp++) {
            float p0[4] = {0.f, 0.f, 0.f, 0.f};
            float p1[4] = {0.f, 0.f, 0.f, 0.f};
#pragma unroll
            for (int kc2 = 0; kc2 < 8; kc2++) {
                uint32_t b0, b1, b2, b3;
                uint32_t base = sbV + (uint32_t)(kc2 * 12 + 2 * ncp) * 512;
                lds128(b0, b1, b2, b3, base);
                mma_bf16(p0[0], p0[1], p0[2], p0[3],
                         af[2 * kc2][0], af[2 * kc2][1],
                         af[2 * kc2][2], af[2 * kc2][3], b0, b1);
                mma_bf16(p0[0], p0[1], p0[2], p0[3],
                         af[2 * kc2 + 1][0], af[2 * kc2 + 1][1],
                         af[2 * kc2 + 1][2], af[2 * kc2 + 1][3], b2, b3);
                lds128(b0, b1, b2, b3, base + 512);
                mma_bf16(p1[0], p1[1], p1[2], p1[3],
                         af[2 * kc2][0], af[2 * kc2][1],
                         af[2 * kc2][2], af[2 * kc2][3], b0, b1);
                mma_bf16(p1[0], p1[1], p1[2], p1[3],
                         af[2 * kc2 + 1][0], af[2 * kc2 + 1][1],
                         af[2 * kc2 + 1][2], af[2 * kc2 + 1][3], b2, b3);
            }
            paf[ncp][0] = packbf(p0[0] * av0[ncp], p0[1] * av0[ncp]);
            paf[ncp][1] = packbf(p0[2] * av1[ncp], p0[3] * av1[ncp]);
            paf[ncp][2] = packbf(p1[0] * av0[ncp], p1[1] * av0[ncp]);
            paf[ncp][3] = packbf(p1[2] * av1[ncp], p1[3] * av1[ncp]);
        }

        // ---- U-GEMM: acc += pa @ (P*dt*Uhat)^T ----
#pragma unroll
        for (int i = 0; i < 96; i++) {
            uint32_t b0, b1, b2, b3;
            lds128(b0, b1, b2, b3, sbU + (uint32_t)i * 512);
            int kc2 = i >> 5, nc = i & 31;
            mma_bf16(acc[nc][0], acc[nc][1], acc[nc][2], acc[nc][3],
                     paf[2 * kc2][0], paf[2 * kc2][1],
                     paf[2 * kc2][2], paf[2 * kc2][3], b0, b1);
            mma_bf16(acc[nc][0], acc[nc][1], acc[nc][2], acc[nc][3],
                     paf[2 * kc2 + 1][0], paf[2 * kc2 + 1][1],
                     paf[2 * kc2 + 1][2], paf[2 * kc2 + 1][3], b2, b3);
        }
    }

    float2* o0 = reinterpret_cast<float2*>(out + (size_t)r0 * M_DIM);
    float2* o1 = reinterpret_cast<float2*>(out + (size_t)(r0 + 8) * M_DIM);
#pragma unroll
    for (int nc = 0; nc < 32; nc++) {
        __stcs(&o0[4 * nc + tig], make_float2(acc[nc][0], acc[nc][1]));
        __stcs(&o1[4 * nc + tig], make_float2(acc[nc][2], acc[nc][3]));
    }
}

// ============================================================================
// THE kernel: precompute levels + barriers + main loop.
// ============================================================================
__global__ void __launch_bounds__(256, 1)
koop_all(const float* __restrict__ z_in, const float* __restrict__ a_in,
         const float* __restrict__ Araw, const float* __restrict__ BUraw,
         const float* __restrict__ BVraw, const int* __restrict__ steps_p,
         float* __restrict__ out, int n_tiles) {
    extern __shared__ unsigned char smem[];
    float* sm3 = reinterpret_cast<float*>(smem);
    const unsigned G = gridDim.x;
    int tid = threadIdx.x, wid = tid >> 5, lane = tid & 31;
    int tig = lane & 3, lg = lane >> 2;

    int steps = steps_p ? *steps_p : 8;
    int P = pick_P(steps);
    int passes = (steps > 0) ? steps / P : 0;

    // ---- warm L2 with this CTA's first z tile ----
    if ((int)blockIdx.x < n_tiles) {
        const char* pz = (const char*)(z_in + (size_t)blockIdx.x * TILE_M * M_DIM);
#pragma unroll
        for (int q = 0; q < 4; q++) prefetch_l2(pz + (tid + q * 256) * 128);
    }

    // ================= P0: X2 = X*X (xform) + init =================
    for (int it = blockIdx.x; it < 128; it += G) {
        if (it < 64) {
            gemm_tile(Araw, Araw, g_X2, 256, false, true,
                      (it >> 3) * 32, (it & 7) * 32, sm3);
        } else {
            int c = it - 64;
            for (int i = tid; i < 1024; i += 256) {
                int id = c * 1024 + i;
                int n = id >> 8, k = id & 255;
                g_X[id] = DT_C * Araw[id] + (n == k ? 1.f : 0.f);
            }
            for (int i = tid; i < 384; i += 256) {
                int id = c * 384 + i;
                int m = id / 96, lr = id % 96, l = lr >> 4, ri = lr & 15;
                g_Um[id] = tanhf(BUraw[(l * 256 + m) * 16 + ri]) * BMAX_C;
                g_Vm[id] = tanhf(BVraw[(l * 256 + m) * 16 + ri]) * BMAX_C;
            }
        }
    }
    grid_barrier(G);

    // ================= P1: X4 = X2*X2 ; T = X2^T*Vm =================
    for (int it = blockIdx.x; it < 88; it += G) {
        if (it < 64) {
            gemm_tile(g_X2, g_X2, g_X4, 256, false, false,
                      (it >> 3) * 32, (it & 7) * 32, sm3);
        } else {
            int t = it - 64;
            int r0 = (t / 3) * 32, c0 = (t % 3) * 32;
            if (P == 8) gemm_tile(g_X2, g_Vm, g_T, 96, true, false, r0, c0, sm3);
            else        copy_tile(g_Vm, g_T, 96, r0, c0);
        }
    }
    grid_barrier(G);

    // ============ P2: X8 = X4*X4 ; Uh = E1*Um ; Vh = X^T*T ============
    for (int it = blockIdx.x; it < 112; it += G) {
        if (it < 64) {
            gemm_tile(g_X4, g_X4, g_X8, 256, false, false,
                      (it >> 3) * 32, (it & 7) * 32, sm3);
        } else if (it < 88) {
            int t = it - 64;
            int r0 = (t / 3) * 32, c0 = (t % 3) * 32;
            if      (P == 8) gemm_tile(g_X4, g_Um, g_Uh, 96, false, false, r0, c0, sm3);
            else if (P == 4) gemm_tile(g_X2, g_Um, g_Uh, 96, false, false, r0, c0, sm3);
            else if (P == 2) gemm_tile(g_X,  g_Um, g_Uh, 96, false, false, r0, c0, sm3);
            else             copy_tile(g_Um, g_Uh, 96, r0, c0);
        } else {
            int t = it - 88;
            int r0 = (t / 3) * 32, c0 = (t % 3) * 32;
            if (P >= 4) gemm_tile(g_X, g_T, g_Vh, 96, true, false, r0, c0, sm3);
            else        copy_tile(g_T, g_Vh, 96, r0, c0);
        }
    }
    grid_barrier(G);

    // ================= P3: fragment images -> g_wfrag =================
    {
        const float* AP = (P == 8) ? g_X8 : (P == 4) ? g_X4
                        : (P == 2) ? g_X2 : g_X;
        float coefU = (float)P * DT_C;
        for (int id = blockIdx.x * 256 + tid; id < W_TOTAL / 4; id += G * 256) {
            int r = id & 3, ln = (id >> 2) & 31, rest = id >> 7;
            int tg = ln & 3, lgr = ln >> 2;
            int kodd = r >> 1, breg = r & 1;
            float lo, hi;
            if (id < BA_BYTES / 4) {
                int nc = rest & 31, kc2 = rest >> 5;
                int n  = 8 * nc + lgr;
                int k0 = 16 * (2 * kc2 + kodd) + tg * 2 + breg * 8;
                lo = AP[n * 256 + k0]     - (n == k0     ? 1.f : 0.f);
                hi = AP[n * 256 + k0 + 1] - (n == k0 + 1 ? 1.f : 0.f);
            } else if (id < (BA_BYTES + BV_BYTES) / 4) {
                int rest2 = rest - (BA_BYTES / 512);
                int nc = rest2 % 12, kc2 = rest2 / 12;
                int n  = 8 * nc + lgr;
                int k0 = 16 * (2 * kc2 + kodd) + tg * 2 + breg * 8;
                lo = g_Vh[k0 * 96 + n];
                hi = g_Vh[(k0 + 1) * 96 + n];
            } else {
                int rest3 = rest - ((BA_BYTES + BV_BYTES) / 512);
                int nc = rest3 & 31, kc2 = rest3 >> 5;
                int n  = 8 * nc + lgr;
                int k0 = 16 * (2 * kc2 + kodd) + tg * 2 + breg * 8;
                lo = coefU * g_Uh[n * 96 + k0];
                hi = coefU * g_Uh[n * 96 + k0 + 1];
            }
            reinterpret_cast<uint32_t*>(g_wfrag)[id] = packbf(lo, hi);
        }
    }
    grid_barrier(G);

    // ================= P4: weights -> SMEM, main loop =================
    {
        const uint4* src = reinterpret_cast<const uint4*>(g_wfrag);
        uint4* dst = reinterpret_cast<uint4*>(smem);
        for (int i = tid; i < W_TOTAL / 16; i += 256) dst[i] = src[i];
    }
    __syncthreads();

    const uint32_t sbA = smem_u32(smem) + (uint32_t)lane * 16;
    const uint32_t sbV = sbA + BA_BYTES;
    const uint32_t sbU = sbA + BA_BYTES + BV_BYTES;

    int b = (int)blockIdx.x;
    int nrem  = n_tiles % (int)G;        // 72 for n_tiles=2048, G=152
    int nfull = n_tiles - nrem;          // 1976

    // uniform full-tile rounds (every CTA gets exactly nfull/G tiles)
    for (int tile = b; tile < nfull; tile += (int)G) {
        int nt = tile + (int)G;
        int pf = (nt < n_tiles) ? nt * TILE_M + wid * 16 : -1;
        koop_tile(z_in, a_in, out, tile * TILE_M + wid * 16 + lg, pf,
                  sbA, sbV, sbU, passes, tig, lane);
    }

    // tail: split remaining tiles into half-tiles (64 rows, warps 0-3)
    if (nrem > 0) {
        if (2 * nrem <= (int)G) {
            if (b < 2 * nrem && wid < 4) {
                int tile = nfull + (b >> 1);
                int r0 = tile * TILE_M + (b & 1) * 64 + wid * 16 + lg;
                koop_tile(z_in, a_in, out, r0, -1,
                          sbA, sbV, sbU, passes, tig, lane);
            }
        } else if (b < nrem) {
            koop_tile(z_in, a_in, out, (nfull + b) * TILE_M + wid * 16 + lg,
                      -1, sbA, sbV, sbU, passes, tig, lane);
        }
    }
}

// ============================================================================
// kernel_launch — graph-capturable: ONE kernel launch, no sync, no alloc.
// ============================================================================
extern "C" void kernel_launch(void* const* d_in, const int* in_sizes, int n_in,
                              void* d_out, int out_size) {
    const float* z  = (const float*)d_in[0];
    const float* a  = (const float*)d_in[1];
    const float* A  = (const float*)d_in[2];
    const float* BU = (const float*)d_in[3];
    const float* BV = (const float*)d_in[4];
    const int* steps = (n_in > 5) ? (const int*)d_in[5] : nullptr;

    int n_rows  = in_sizes[0] / M_DIM;
    int n_tiles = n_rows / TILE_M;

    cudaFuncSetAttribute(koop_all, cudaFuncAttributeMaxDynamicSharedMemorySize,
                         W_TOTAL);

    int dev = 0, sm_count = 0;
    cudaGetDevice(&dev);
    cudaDeviceGetAttribute(&sm_count, cudaDevAttrMultiProcessorCount, dev);
    if (sm_count <= 0) sm_count = 148;
    // 229KB SMEM -> exactly 1 CTA/SM; grid = sm_count guarantees co-residency.
    int grid = sm_count;

    koop_all<<<grid, 256, W_TOTAL>>>(z, a, A, BU, BV, steps,
                                     (float*)d_out, n_tiles);
}